// round 10
// baseline (speedup 1.0000x reference)
#include <cuda_runtime.h>
#include <math.h>

#define D_DIM 131072
#define K_SEL 5
#define ELEMS 16                      // elements per thread (512 per warp)
#define WARPS_PER_ROW 256             // D_DIM / 512
#define TPB 256
#define MAX_B 128
#define NCAND (WARPS_PER_ROW * K_SEL) // 1280 candidates per row
#define CTAS_PER_B 32                 // 256 warps / 8 warps per CTA
#define ZBUF_BYTES 16384              // 16KB smem zero buffer
// per-CTA fill slice: (K_SEL * D_DIM * 4) / CTAS_PER_B = 81920 = 5 x 16KB
#define FILL_SLICE_BYTES (K_SEL * D_DIM * 4 / CTAS_PER_B)
#define FILL_OPS (FILL_SLICE_BYTES / ZBUF_BYTES)   // 5

// inter-CTA scratch (no allocations allowed)
__device__ unsigned long long g_cand[MAX_B * NCAND];
__device__ int g_arrive[MAX_B];   // zero-initialized; self-resetting per replay

// monotonic float->uint transform (order-preserving incl. negatives)
__device__ __forceinline__ unsigned ford(float f) {
    unsigned u = __float_as_uint(f);
    return u ^ (((int)u >> 31) | 0x80000000u);
}

// element id e (0..15) -> global index within the row
__device__ __forceinline__ int eidx(int base, int lane, int e) {
    return base + ((lane + (e >> 2) * 32) << 2) + (e & 3);
}

// ---------------------------------------------------------------------------
// Single fused kernel (R9 structure + L2 policy steering):
//   writes: TMA bulk stores with L2::evict_last  -> output lines stay in L2
//           across graph replays, DRAM write traffic collapses in steady state
//   reads:  single-use sims loads with L2::evict_first -> never displace
//           pending output lines
// ---------------------------------------------------------------------------
__global__ void __launch_bounds__(TPB, 3)
fused_topk_fill(const float* __restrict__ sims,
                float* __restrict__ out,
                int idx_off) {
    __shared__ float4 zbuf[ZBUF_BYTES / 16];
    __shared__ unsigned long long s_warp[8];
    __shared__ unsigned long long s_win;
    __shared__ int s_last;
    const int t = threadIdx.x;
    const int b_row = blockIdx.x / CTAS_PER_B;

    unsigned long long pol_last, pol_first;
    asm("createpolicy.fractional.L2::evict_last.b64 %0, 1.0;"  : "=l"(pol_last));
    asm("createpolicy.fractional.L2::evict_first.b64 %0, 1.0;" : "=l"(pol_first));

    // ---- zero the smem staging buffer ----
    const float4 z = make_float4(0.f, 0.f, 0.f, 0.f);
#pragma unroll
    for (int i = t; i < ZBUF_BYTES / 16; i += TPB) zbuf[i] = z;
    __syncthreads();
    asm volatile("fence.proxy.async.shared::cta;" ::: "memory");

    // ---- issue async fill: FILL_OPS x 16KB bulk stores, evict_last ----
    char* dst = (char*)(out + idx_off) +
                (long long)blockIdx.x * FILL_SLICE_BYTES;
    if (t < FILL_OPS) {
        unsigned saddr = (unsigned)__cvta_generic_to_shared(zbuf);
        asm volatile(
            "cp.async.bulk.global.shared::cta.bulk_group.L2::cache_hint "
            "[%0], [%1], %2, %3;"
            :: "l"(dst + t * ZBUF_BYTES), "r"(saddr), "r"(ZBUF_BYTES),
               "l"(pol_last)
            : "memory");
        asm volatile("cp.async.bulk.commit_group;" ::: "memory");
    }

    // ---------------- top-k stage1 (overlaps with TMA drain) ----------------
    const int gw   = (blockIdx.x * TPB + t) >> 5;
    const int lane = t & 31;
    const int w    = gw % WARPS_PER_ROW;
    const int base = w * (ELEMS * 32);       // 512 elems per warp
    const float* p = sims + (size_t)b_row * D_DIM + base;

    // 4 back-to-back LDG.128, evict_first (single-use stream)
    float c[ELEMS];
#pragma unroll
    for (int i = 0; i < 4; i++) {
        asm("ld.global.nc.L2::cache_hint.v4.f32 {%0,%1,%2,%3}, [%4], %5;"
            : "=f"(c[4*i]), "=f"(c[4*i+1]), "=f"(c[4*i+2]), "=f"(c[4*i+3])
            : "l"(p + (lane + i * 32) * 4), "l"(pol_first));
    }

    // per-thread argmax over 16 elems: track value + 4-bit element id only.
    // e increases with global index, so strict > keeps the lowest index.
    float bv = -INFINITY; int be = 0;
#pragma unroll
    for (int e = 0; e < ELEMS; e++)
        if (c[e] > bv) { bv = c[e]; be = e; }
    int bi = eidx(base, lane, be);

    unsigned dead = 0u;
#pragma unroll
    for (int rr = 0; rr < K_SEL; rr++) {
        float wv = bv; int wi = bi;
#pragma unroll
        for (int off = 16; off >= 1; off >>= 1) {
            float ov = __shfl_down_sync(0xffffffffu, wv, off);
            int   oi = __shfl_down_sync(0xffffffffu, wi, off);
            if (ov > wv || (ov == wv && oi < wi)) { wv = ov; wi = oi; }
        }
        wv = __shfl_sync(0xffffffffu, wv, 0);
        wi = __shfl_sync(0xffffffffu, wi, 0);

        if (lane == rr)
            g_cand[(b_row * WARPS_PER_ROW + w) * K_SEL + rr] =
                ((unsigned long long)ford(wv) << 32) | (unsigned)(~wi);

        if (bi == wi) {                   // exactly one lane owns the winner
            dead |= (1u << be);
            bv = -INFINITY; be = 0;
#pragma unroll
            for (int e = 0; e < ELEMS; e++) {
                float val = ((dead >> e) & 1u) ? -INFINITY : c[e];
                if (val > bv) { bv = val; be = e; }
            }
            bi = eidx(base, lane, be);
        }
    }

    // ---- drain this CTA's fill stores, publish, take row ticket ----
    if (t < FILL_OPS)
        asm volatile("cp.async.bulk.wait_group 0;" ::: "memory");
    __syncthreads();
    __threadfence();                      // publish g_cand + fill completion
    if (t == 0)
        s_last = (atomicAdd(&g_arrive[b_row], 1) == CTAS_PER_B - 1);
    __syncthreads();
    if (!s_last) return;

    // =============== last CTA of this row: merge + scatter ===============
    __threadfence();                      // acquire other CTAs' writes

    // thread t holds candidates t + s*256, s=0..4 ; 0 = dead
    unsigned long long k[5];
#pragma unroll
    for (int s = 0; s < 5; s++)
        k[s] = g_cand[b_row * NCAND + t + s * 256];

    const int wid = t >> 5;
#pragma unroll
    for (int rr = 0; rr < K_SEL; rr++) {
        unsigned long long m = k[0];
#pragma unroll
        for (int s = 1; s < 5; s++) if (k[s] > m) m = k[s];
#pragma unroll
        for (int off = 16; off >= 1; off >>= 1) {
            unsigned long long o = __shfl_down_sync(0xffffffffu, m, off);
            if (o > m) m = o;
        }
        if (lane == 0) s_warp[wid] = m;
        __syncthreads();
        if (t < 32) {
            unsigned long long f = (lane < 8) ? s_warp[lane] : 0ull;
#pragma unroll
            for (int off = 4; off >= 1; off >>= 1) {
                unsigned long long o = __shfl_down_sync(0xffffffffu, f, off);
                if (o > f) f = o;
            }
            if (lane == 0) s_win = f;
        }
        __syncthreads();
        unsigned long long win = s_win;
#pragma unroll
        for (int s = 0; s < 5; s++) if (k[s] == win) k[s] = 0ull;
        if (t == 0) {
            int idx = (int)(~(unsigned)win);
            if (idx_off > 0) out[b_row * K_SEL + rr] = (float)idx;
            out[(size_t)idx_off + ((size_t)b_row * K_SEL + rr) * D_DIM + idx]
                = 1.0f;
        }
        __syncthreads();
    }

    if (t == 0) g_arrive[b_row] = 0;      // reset for next graph replay
}

extern "C" void kernel_launch(void* const* d_in, const int* in_sizes, int n_in,
                              void* d_out, int out_size) {
    const float* sims = (const float*)d_in[0];
    int B = in_sizes[0] / D_DIM;
    if (B < 1) B = 1;
    if (B > MAX_B) B = MAX_B;

    long long soft = (long long)B * K_SEL * D_DIM;
    long long idx_off_ll = (long long)out_size - soft;
    int idx_off = (idx_off_ll > 0) ? (int)idx_off_ll : 0;

    fused_topk_fill<<<B * CTAS_PER_B, TPB>>>(sims, (float*)d_out, idx_off);
}

// round 11
// speedup vs baseline: 1.0125x; 1.0125x over previous
#include <cuda_runtime.h>
#include <math.h>

#define D_DIM 131072
#define K_SEL 5
#define ELEMS 16                      // elements per thread (512 per warp)
#define WARPS_PER_ROW 256             // D_DIM / 512
#define TPB 256
#define MAX_B 128
#define NCAND (WARPS_PER_ROW * K_SEL) // 1280 candidates per row
#define CTAS_PER_B 32                 // 256 warps / 8 warps per CTA
#define ZBUF_BYTES 16384              // 16KB smem zero buffer
// per-CTA fill slice: (K_SEL * D_DIM * 4) / CTAS_PER_B = 81920 = 5 x 16KB
#define FILL_SLICE_BYTES (K_SEL * D_DIM * 4 / CTAS_PER_B)
#define FILL_OPS (FILL_SLICE_BYTES / ZBUF_BYTES)   // 5

// inter-CTA scratch (no allocations allowed)
__device__ unsigned long long g_cand[MAX_B * NCAND];
__device__ int g_arrive[MAX_B];   // zero-initialized; self-resetting per replay

// monotonic float->uint transform (order-preserving incl. negatives)
__device__ __forceinline__ unsigned ford(float f) {
    unsigned u = __float_as_uint(f);
    return u ^ (((int)u >> 31) | 0x80000000u);
}

// element id e (0..15) -> global index within the row
__device__ __forceinline__ int eidx(int base, int lane, int e) {
    return base + ((lane + (e >> 2) * 32) << 2) + (e & 3);
}

// ---------------------------------------------------------------------------
// Single fused kernel with PARTITIONED L2 pinning:
//   - first PIN fraction of fill slices (~96MB < 126MB L2): evict_last
//     -> stay resident across graph replays, re-writes become L2 hits,
//        zero DRAM traffic for that region in steady state
//   - remaining slices + all sims reads: evict_first
//     -> streaming traffic cannot displace the pinned set
// ---------------------------------------------------------------------------
__global__ void __launch_bounds__(TPB, 3)
fused_topk_fill(const float* __restrict__ sims,
                float* __restrict__ out,
                int idx_off, int pin_ctas) {
    __shared__ float4 zbuf[ZBUF_BYTES / 16];
    __shared__ unsigned long long s_warp[8];
    __shared__ unsigned long long s_win;
    __shared__ int s_last;
    const int t = threadIdx.x;
    const int b_row = blockIdx.x / CTAS_PER_B;

    unsigned long long pol_last, pol_first;
    asm("createpolicy.fractional.L2::evict_last.b64 %0, 1.0;"  : "=l"(pol_last));
    asm("createpolicy.fractional.L2::evict_first.b64 %0, 1.0;" : "=l"(pol_first));
    const unsigned long long pol_w =
        ((int)blockIdx.x < pin_ctas) ? pol_last : pol_first;

    // ---- zero the smem staging buffer ----
    const float4 z = make_float4(0.f, 0.f, 0.f, 0.f);
#pragma unroll
    for (int i = t; i < ZBUF_BYTES / 16; i += TPB) zbuf[i] = z;
    __syncthreads();
    asm volatile("fence.proxy.async.shared::cta;" ::: "memory");

    // ---- issue async fill: FILL_OPS x 16KB bulk stores ----
    char* dst = (char*)(out + idx_off) +
                (long long)blockIdx.x * FILL_SLICE_BYTES;
    if (t < FILL_OPS) {
        unsigned saddr = (unsigned)__cvta_generic_to_shared(zbuf);
        asm volatile(
            "cp.async.bulk.global.shared::cta.bulk_group.L2::cache_hint "
            "[%0], [%1], %2, %3;"
            :: "l"(dst + t * ZBUF_BYTES), "r"(saddr), "r"(ZBUF_BYTES),
               "l"(pol_w)
            : "memory");
        asm volatile("cp.async.bulk.commit_group;" ::: "memory");
    }

    // ---------------- top-k stage1 (overlaps with TMA drain) ----------------
    const int gw   = (blockIdx.x * TPB + t) >> 5;
    const int lane = t & 31;
    const int w    = gw % WARPS_PER_ROW;
    const int base = w * (ELEMS * 32);       // 512 elems per warp
    const float* p = sims + (size_t)b_row * D_DIM + base;

    // 4 back-to-back LDG.128, evict_first (single-use stream)
    float c[ELEMS];
#pragma unroll
    for (int i = 0; i < 4; i++) {
        asm("ld.global.nc.L2::cache_hint.v4.f32 {%0,%1,%2,%3}, [%4], %5;"
            : "=f"(c[4*i]), "=f"(c[4*i+1]), "=f"(c[4*i+2]), "=f"(c[4*i+3])
            : "l"(p + (lane + i * 32) * 4), "l"(pol_first));
    }

    // per-thread argmax over 16 elems: value + 4-bit element id only.
    // e increases with global index, so strict > keeps the lowest index.
    float bv = -INFINITY; int be = 0;
#pragma unroll
    for (int e = 0; e < ELEMS; e++)
        if (c[e] > bv) { bv = c[e]; be = e; }
    int bi = eidx(base, lane, be);

    unsigned dead = 0u;
#pragma unroll
    for (int rr = 0; rr < K_SEL; rr++) {
        float wv = bv; int wi = bi;
#pragma unroll
        for (int off = 16; off >= 1; off >>= 1) {
            float ov = __shfl_down_sync(0xffffffffu, wv, off);
            int   oi = __shfl_down_sync(0xffffffffu, wi, off);
            if (ov > wv || (ov == wv && oi < wi)) { wv = ov; wi = oi; }
        }
        wv = __shfl_sync(0xffffffffu, wv, 0);
        wi = __shfl_sync(0xffffffffu, wi, 0);

        if (lane == rr)
            g_cand[(b_row * WARPS_PER_ROW + w) * K_SEL + rr] =
                ((unsigned long long)ford(wv) << 32) | (unsigned)(~wi);

        if (bi == wi) {                   // exactly one lane owns the winner
            dead |= (1u << be);
            bv = -INFINITY; be = 0;
#pragma unroll
            for (int e = 0; e < ELEMS; e++) {
                float val = ((dead >> e) & 1u) ? -INFINITY : c[e];
                if (val > bv) { bv = val; be = e; }
            }
            bi = eidx(base, lane, be);
        }
    }

    // ---- drain this CTA's fill stores, publish, take row ticket ----
    if (t < FILL_OPS)
        asm volatile("cp.async.bulk.wait_group 0;" ::: "memory");
    __syncthreads();
    __threadfence();                      // publish g_cand + fill completion
    if (t == 0)
        s_last = (atomicAdd(&g_arrive[b_row], 1) == CTAS_PER_B - 1);
    __syncthreads();
    if (!s_last) return;

    // =============== last CTA of this row: merge + scatter ===============
    __threadfence();                      // acquire other CTAs' writes

    // thread t holds candidates t + s*256, s=0..4 ; 0 = dead
    unsigned long long k[5];
#pragma unroll
    for (int s = 0; s < 5; s++)
        k[s] = g_cand[b_row * NCAND + t + s * 256];

    const int wid = t >> 5;
#pragma unroll
    for (int rr = 0; rr < K_SEL; rr++) {
        unsigned long long m = k[0];
#pragma unroll
        for (int s = 1; s < 5; s++) if (k[s] > m) m = k[s];
#pragma unroll
        for (int off = 16; off >= 1; off >>= 1) {
            unsigned long long o = __shfl_down_sync(0xffffffffu, m, off);
            if (o > m) m = o;
        }
        if (lane == 0) s_warp[wid] = m;
        __syncthreads();
        if (t < 32) {
            unsigned long long f = (lane < 8) ? s_warp[lane] : 0ull;
#pragma unroll
            for (int off = 4; off >= 1; off >>= 1) {
                unsigned long long o = __shfl_down_sync(0xffffffffu, f, off);
                if (o > f) f = o;
            }
            if (lane == 0) s_win = f;
        }
        __syncthreads();
        unsigned long long win = s_win;
#pragma unroll
        for (int s = 0; s < 5; s++) if (k[s] == win) k[s] = 0ull;
        if (t == 0) {
            int idx = (int)(~(unsigned)win);
            if (idx_off > 0) out[b_row * K_SEL + rr] = (float)idx;
            out[(size_t)idx_off + ((size_t)b_row * K_SEL + rr) * D_DIM + idx]
                = 1.0f;
        }
        __syncthreads();
    }

    if (t == 0) g_arrive[b_row] = 0;      // reset for next graph replay
}

extern "C" void kernel_launch(void* const* d_in, const int* in_sizes, int n_in,
                              void* d_out, int out_size) {
    const float* sims = (const float*)d_in[0];
    int B = in_sizes[0] / D_DIM;
    if (B < 1) B = 1;
    if (B > MAX_B) B = MAX_B;

    long long soft = (long long)B * K_SEL * D_DIM;
    long long idx_off_ll = (long long)out_size - soft;
    int idx_off = (idx_off_ll > 0) ? (int)idx_off_ll : 0;

    int grid = B * CTAS_PER_B;
    // pin ~60% of the output region (~96MB for B=64) -> fits in 126MB L2
    int pin_ctas = (grid * 3) / 5;

    fused_topk_fill<<<grid, TPB>>>(sims, (float*)d_out, idx_off, pin_ctas);
}

// round 13
// speedup vs baseline: 1.0133x; 1.0008x over previous
#include <cuda_runtime.h>
#include <math.h>

#define D_DIM 131072
#define K_SEL 5
#define ELEMS 16                      // elements per thread (512 per warp)
#define WARPS_PER_ROW 256             // D_DIM / 512
#define TPB 256
#define MAX_B 128
#define NCAND (WARPS_PER_ROW * K_SEL) // 1280 candidates per row
#define CTAS_PER_B 32                 // 256 warps / 8 warps per CTA
#define ZBUF_BYTES 16384              // 16KB smem zero buffer
#define FILL_SLICE_BYTES (K_SEL * D_DIM * 4 / CTAS_PER_B)  // 81920
#define FILL_OPS (FILL_SLICE_BYTES / ZBUF_BYTES)           // 5

// inter-CTA scratch (no allocations allowed)
__device__ unsigned long long g_cand[MAX_B * NCAND];
__device__ int g_arrive[MAX_B];   // zero-initialized; self-resetting per replay

// monotonic float->uint transform (order-preserving incl. negatives)
__device__ __forceinline__ unsigned ford(float f) {
    unsigned u = __float_as_uint(f);
    return u ^ (((int)u >> 31) | 0x80000000u);
}

// element id e (0..15) -> global index within the row (monotonic in e)
__device__ __forceinline__ int eidx(int base, int lane, int e) {
    return base + ((lane + (e >> 2) * 32) << 2) + (e & 3);
}

__device__ __forceinline__ unsigned redux_max_u32(unsigned v) {
    unsigned r;
    asm("redux.sync.max.u32 %0, %1, 0xffffffff;" : "=r"(r) : "r"(v));
    return r;
}
__device__ __forceinline__ int redux_min_s32(int v) {
    int r;
    asm("redux.sync.min.s32 %0, %1, 0xffffffff;" : "=r"(r) : "r"(v));
    return r;
}

// ---------------------------------------------------------------------------
// Single fused kernel (R9 structure, slim select):
//   1. async TMA zero-fill slice (write stream drains in background)
//   2. warp top-5 via redux.sync argmax + per-thread top-2 (rescans rare)
//   3. row ticket; last CTA merges 1280 candidates, writes indices+one-hots
// ---------------------------------------------------------------------------
__global__ void __launch_bounds__(TPB, 3)
fused_topk_fill(const float* __restrict__ sims,
                float* __restrict__ out,
                int idx_off) {
    __shared__ float4 zbuf[ZBUF_BYTES / 16];
    __shared__ unsigned long long s_warp[8];
    __shared__ unsigned long long s_win;
    __shared__ int s_last;
    const int t = threadIdx.x;
    const int b_row = blockIdx.x / CTAS_PER_B;

    // ---- zero the smem staging buffer ----
    const float4 z = make_float4(0.f, 0.f, 0.f, 0.f);
#pragma unroll
    for (int i = t; i < ZBUF_BYTES / 16; i += TPB) zbuf[i] = z;
    __syncthreads();
    asm volatile("fence.proxy.async.shared::cta;" ::: "memory");

    // ---- issue async fill: FILL_OPS x 16KB bulk stores (threads 0..4) ----
    char* dst = (char*)(out + idx_off) +
                (long long)blockIdx.x * FILL_SLICE_BYTES;
    if (t < FILL_OPS) {
        unsigned saddr = (unsigned)__cvta_generic_to_shared(zbuf);
        asm volatile(
            "cp.async.bulk.global.shared::cta.bulk_group [%0], [%1], %2;"
            :: "l"(dst + t * ZBUF_BYTES), "r"(saddr), "r"(ZBUF_BYTES)
            : "memory");
        asm volatile("cp.async.bulk.commit_group;" ::: "memory");
    }

    // ---------------- top-k stage1 (overlaps with TMA drain) ----------------
    const int gw   = (blockIdx.x * TPB + t) >> 5;
    const int lane = t & 31;
    const int w    = gw % WARPS_PER_ROW;
    const int base = w * (ELEMS * 32);       // 512 elems per warp
    const float4* p = reinterpret_cast<const float4*>(
        sims + (size_t)b_row * D_DIM + base);

    // 4 back-to-back LDG.128
    float4 r[4];
#pragma unroll
    for (int i = 0; i < 4; i++) r[i] = p[lane + i * 32];

    float c[ELEMS];
#pragma unroll
    for (int i = 0; i < 4; i++) {
        c[4*i+0] = r[i].x; c[4*i+1] = r[i].y;
        c[4*i+2] = r[i].z; c[4*i+3] = r[i].w;
    }

    // ---- per-thread top-1 (strict > keeps lowest index) ----
    float bv = -INFINITY; int be = 0;
#pragma unroll
    for (int e = 0; e < ELEMS; e++)
        if (c[e] > bv) { bv = c[e]; be = e; }
    int bi = eidx(base, lane, be);

    // ---- per-thread top-2 (skip be) ----
    float sv = -INFINITY; int se = 0;
#pragma unroll
    for (int e = 0; e < ELEMS; e++) {
        float val = (e == be) ? -INFINITY : c[e];
        if (val > sv) { sv = val; se = e; }
    }
    bool have2 = true;

    unsigned dead = 0u;
#pragma unroll
    for (int rr = 0; rr < K_SEL; rr++) {
        // warp argmax via redux: value first, then lowest index among ties
        unsigned key  = ford(bv);
        unsigned wkey = redux_max_u32(key);
        int cand = (key == wkey) ? bi : 0x7fffffff;
        int wi   = redux_min_s32(cand);

        if (lane == rr)
            g_cand[(b_row * WARPS_PER_ROW + w) * K_SEL + rr] =
                ((unsigned long long)wkey << 32) | (unsigned)(~wi);

        if (bi == wi) {                   // exactly one lane owns the winner
            dead |= (1u << be);
            if (have2) {                  // cheap promote (typical path)
                bv = sv; be = se; bi = eidx(base, lane, se);
                have2 = false;
            } else {                      // rare: same thread consumed twice+
                bv = -INFINITY; be = 0;
#pragma unroll
                for (int e = 0; e < ELEMS; e++) {
                    float val = ((dead >> e) & 1u) ? -INFINITY : c[e];
                    if (val > bv) { bv = val; be = e; }
                }
                bi = eidx(base, lane, be);
            }
        }
    }

    // ---- drain this CTA's fill stores, publish, take row ticket ----
    if (t < FILL_OPS)
        asm volatile("cp.async.bulk.wait_group 0;" ::: "memory");
    __syncthreads();
    __threadfence();                      // publish g_cand + fill completion
    if (t == 0)
        s_last = (atomicAdd(&g_arrive[b_row], 1) == CTAS_PER_B - 1);
    __syncthreads();
    if (!s_last) return;

    // =============== last CTA of this row: merge + scatter ===============
    __threadfence();                      // acquire other CTAs' writes

    unsigned long long k[5];
#pragma unroll
    for (int s = 0; s < 5; s++)
        k[s] = g_cand[b_row * NCAND + t + s * 256];

    const int wid = t >> 5;
    const int lane2 = t & 31;
#pragma unroll
    for (int rr = 0; rr < K_SEL; rr++) {
        unsigned long long m = k[0];
#pragma unroll
        for (int s = 1; s < 5; s++) if (k[s] > m) m = k[s];
#pragma unroll
        for (int off = 16; off >= 1; off >>= 1) {
            unsigned long long o = __shfl_down_sync(0xffffffffu, m, off);
            if (o > m) m = o;
        }
        if (lane2 == 0) s_warp[wid] = m;
        __syncthreads();
        if (t < 32) {
            unsigned long long f = (lane2 < 8) ? s_warp[lane2] : 0ull;
#pragma unroll
            for (int off = 4; off >= 1; off >>= 1) {
                unsigned long long o = __shfl_down_sync(0xffffffffu, f, off);
                if (o > f) f = o;
            }
            if (lane2 == 0) s_win = f;
        }
        __syncthreads();
        unsigned long long win = s_win;
#pragma unroll
        for (int s = 0; s < 5; s++) if (k[s] == win) k[s] = 0ull;
        if (t == 0) {
            int idx = (int)(~(unsigned)win);
            if (idx_off > 0) out[b_row * K_SEL + rr] = (float)idx;
            out[(size_t)idx_off + ((size_t)b_row * K_SEL + rr) * D_DIM + idx]
                = 1.0f;
        }
        __syncthreads();
    }

    if (t == 0) g_arrive[b_row] = 0;      // reset for next graph replay
}

extern "C" void kernel_launch(void* const* d_in, const int* in_sizes, int n_in,
                              void* d_out, int out_size) {
    const float* sims = (const float*)d_in[0];
    int B = in_sizes[0] / D_DIM;
    if (B < 1) B = 1;
    if (B > MAX_B) B = MAX_B;

    long long soft = (long long)B * K_SEL * D_DIM;
    long long idx_off_ll = (long long)out_size - soft;
    int idx_off = (idx_off_ll > 0) ? (int)idx_off_ll : 0;

    fused_topk_fill<<<B * CTAS_PER_B, TPB>>>(sims, (float*)d_out, idx_off);
}